// round 1
// baseline (speedup 1.0000x reference)
#include <cuda_runtime.h>

// Problem shape (fixed by reference): B=256 students, T=200 steps, Q=1000 questions.
#define NB 256
#define NT 200
#define NQ 1000
#define TM1 (NT - 1)   // 199

// Scratch for per-student loss (no cudaMalloc allowed).
__device__ float g_student_loss[NB];

__device__ __forceinline__ float bce_term(float p, float a) {
    // torch BCELoss: -(a*log(p) + (1-a)*log(1-p)), logs clamped at -100
    float logp   = fmaxf(logf(p), -100.0f);
    float log1mp = fmaxf(log1pf(-p), -100.0f);
    return -(a * logp + (1.0f - a) * log1mp);
}

__global__ __launch_bounds__(256)
void per_student_kernel(const float* __restrict__ logit_c,
                        const float* __restrict__ logit_t,
                        const int*   __restrict__ q_idx,
                        const int*   __restrict__ correct,
                        float*       __restrict__ out) {
    const int b = blockIdx.x;    // student
    const int t = threadIdx.x;   // step index 0..TM1-1 (threads >= TM1 idle)

    __shared__ float s_red[256];
    __shared__ int   s_idx[256];

    float pc = 0.0f, pt = 0.0f, a = 0.0f;
    const bool active = (t < TM1);

    if (active) {
        // q used at step t comes from q_idx[b, t+1]
        const int q = q_idx[b * NT + t + 1];
        const long base = ((long)b * NT + t) * NQ;
        const float lc = __ldg(&logit_c[base + q]);
        const float lt = __ldg(&logit_t[base + q]);
        pc = 1.0f / (1.0f + expf(-lc));
        pt = 1.0f / (1.0f + expf(-lt));
        a  = (float)correct[b * NT + t + 1];
    }

    // ---- reduction 1: last index with pc > 0 (matches reference trim) ----
    s_idx[t] = (active && pc > 0.0f) ? t : -1;
    __syncthreads();
    #pragma unroll
    for (int s = 128; s > 0; s >>= 1) {
        if (t < s) s_idx[t] = max(s_idx[t], s_idx[t + s]);
        __syncthreads();
    }
    int last = s_idx[0];
    if (last < 0) last = TM1 - 1;   // reference: all-invalid -> full mask
    const float count = (float)(last + 1);
    __syncthreads();

    // ---- outputs + masked BCE sum ----
    float e = 0.0f;
    if (active) {
        out[1 + b * TM1 + t]             = 0.5f * (pt + pc);  // p_mean
        out[1 + NB * TM1 + b * TM1 + t]  = a;                 // ground_truth
        if (t <= last) {
            e = bce_term(pt, a) + bce_term(pc, a);
        }
    }

    s_red[t] = e;
    __syncthreads();
    #pragma unroll
    for (int s = 128; s > 0; s >>= 1) {
        if (t < s) s_red[t] += s_red[t + s];
        __syncthreads();
    }
    if (t == 0) g_student_loss[b] = s_red[0] / count;
}

__global__ __launch_bounds__(256)
void final_loss_kernel(float* __restrict__ out) {
    const int t = threadIdx.x;
    __shared__ float s_red[256];
    s_red[t] = g_student_loss[t];   // NB == 256 exactly
    __syncthreads();
    #pragma unroll
    for (int s = 128; s > 0; s >>= 1) {
        if (t < s) s_red[t] += s_red[t + s];
        __syncthreads();
    }
    if (t == 0) out[0] = s_red[0];
}

extern "C" void kernel_launch(void* const* d_in, const int* in_sizes, int n_in,
                              void* d_out, int out_size) {
    const float* logit_c = (const float*)d_in[0];
    const float* logit_t = (const float*)d_in[1];
    const int*   q_idx   = (const int*)d_in[2];
    const int*   correct = (const int*)d_in[3];
    float* out = (float*)d_out;

    per_student_kernel<<<NB, 256>>>(logit_c, logit_t, q_idx, correct, out);
    final_loss_kernel<<<1, 256>>>(out);
}